// round 10
// baseline (speedup 1.0000x reference)
#include <cuda_runtime.h>
#include <math.h>

#define NS 100000
#define H 128
#define NBLK 444             // 3 blocks/SM * 148 SMs
#define NTHREADS 256
#define WPB 8
#define TROWS 44             // rows per tile
#define ROWU 33              // padded row stride in float4 units (528B) -> conflict-free
// 100000 = 444*225 + 100
#define BASE_ROWS 225
#define EXTRA 100

__device__ float g_part[6][NBLK];
__device__ int g_count = 0;

__device__ __forceinline__ float d4(float4 a, float4 b) {
    return a.x * b.x + a.y * b.y + a.z * b.z + a.w * b.w;
}
__device__ __forceinline__ void cp16(unsigned daddr, const void* gptr) {
    asm volatile("cp.async.cg.shared.global [%0], [%1], 16;" :: "r"(daddr), "l"(gptr));
}

__global__ __launch_bounds__(NTHREADS, 3) void fp_r10(
    const float* __restrict__ e, const float* __restrict__ q,
    const float* __restrict__ mu_w, const float* __restrict__ sigma_w,
    const float* __restrict__ w_key, const float* __restrict__ w_value,
    const float* __restrict__ mu_b, const float* __restrict__ sigma_b,
    float* __restrict__ out) {
    __shared__ float4 sbuf[2][TROWS * ROWU];   // 2 x 23232 B
    __shared__ float wsum[WPB][6];
    __shared__ int is_last;

    const int tid = threadIdx.x;
    const int lane = tid & 31;
    const int warp = tid >> 5;
    const int o = lane >> 3;      // oct: which of 4 rows
    const int s = lane & 7;       // position within oct: 16 interleaved columns
    const int b = blockIdx.x;
    const int cnt = BASE_ROWS + (b < EXTRA ? 1 : 0);
    const int start = b * BASE_ROWS + (b < EXTRA ? b : EXTRA);
    const int ntiles = (cnt + TROWS - 1) / TROWS;

    // q fragment: units {s, s+8, s+16, s+24}, pre-scaled by 1/||q||
    const float4* __restrict__ q4 = reinterpret_cast<const float4*>(q);
    float4 qv[4];
#pragma unroll
    for (int k = 0; k < 4; k++) qv[k] = q4[s + 8 * k];
    float qn = 0.f;
#pragma unroll
    for (int k = 0; k < 4; k++) qn += d4(qv[k], qv[k]);
    qn += __shfl_xor_sync(0xffffffffu, qn, 1);
    qn += __shfl_xor_sync(0xffffffffu, qn, 2);
    qn += __shfl_xor_sync(0xffffffffu, qn, 4);   // oct covers all 128 cols
    const float rq = rsqrtf(qn);
#pragma unroll
    for (int k = 0; k < 4; k++) {
        qv[k].x *= rq; qv[k].y *= rq; qv[k].z *= rq; qv[k].w *= rq;
    }

    unsigned sb[2];
    sb[0] = (unsigned)__cvta_generic_to_shared(&sbuf[0][0]);
    sb[1] = (unsigned)__cvta_generic_to_shared(&sbuf[1][0]);

    float pp[16], pm[16];
#pragma unroll
    for (int i = 0; i < 16; i++) { pp[i] = 0.f; pm[i] = 0.f; }
    float sp = 0.f, sm = 0.f;

    // prologue: copy tile 0
    {
        const int tcnt = (cnt < TROWS) ? cnt : TROWS;
        const char* src = (const char*)e + (size_t)start * 512;
        for (int idx = tid; idx < tcnt * 32; idx += NTHREADS) {
            int r = idx >> 5, j = idx & 31;
            cp16(sb[0] + (r * ROWU + j) * 16, src + r * 512 + j * 16);
        }
        asm volatile("cp.async.commit_group;");
    }

    for (int t = 0; t < ntiles; t++) {
        const int bufi = t & 1;
        const int tcnt = (cnt - t * TROWS < TROWS) ? (cnt - t * TROWS) : TROWS;

        if (t + 1 < ntiles) {
            const int ncnt = (cnt - (t + 1) * TROWS < TROWS) ? (cnt - (t + 1) * TROWS) : TROWS;
            const char* src = (const char*)e + (size_t)(start + (t + 1) * TROWS) * 512;
            const unsigned dst = sb[bufi ^ 1];
            for (int idx = tid; idx < ncnt * 32; idx += NTHREADS) {
                int r = idx >> 5, j = idx & 31;
                cp16(dst + (r * ROWU + j) * 16, src + r * 512 + j * 16);
            }
            asm volatile("cp.async.commit_group;");
            asm volatile("cp.async.wait_group 1;");
        } else {
            asm volatile("cp.async.wait_group 0;");
        }
        __syncthreads();   // tile t visible to all

        // single-pass compute: oct per row, 4 rows per warp-iteration
        const float4* tile = &sbuf[bufi][0];
        for (int r = warp * 4; r < tcnt; r += WPB * 4) {
            int rr = r + o;
            bool valid = rr < tcnt;
            int rc = valid ? rr : (tcnt - 1);
            const float4* rowp = tile + rc * ROWU;
            float4 a0 = rowp[s];
            float4 a1 = rowp[s + 8];
            float4 a2 = rowp[s + 16];
            float4 a3 = rowp[s + 24];
            float d = d4(a0, qv[0]) + d4(a1, qv[1]) + d4(a2, qv[2]) + d4(a3, qv[3]);
            float n = d4(a0, a0) + d4(a1, a1) + d4(a2, a2) + d4(a3, a3);
            d += __shfl_xor_sync(0xffffffffu, d, 1);
            n += __shfl_xor_sync(0xffffffffu, n, 1);
            d += __shfl_xor_sync(0xffffffffu, d, 2);
            n += __shfl_xor_sync(0xffffffffu, n, 2);
            d += __shfl_xor_sync(0xffffffffu, d, 4);
            n += __shfl_xor_sync(0xffffffffu, n, 4);
            float rn = rsqrtf(n);
            float ap = fmaxf(d, 0.f) * rn;
            float am = fmaxf(-d, 0.f) * rn;
            if (!valid) { ap = 0.f; am = 0.f; }
            sp += ap;  sm += am;
            pp[0]  += ap * a0.x;  pm[0]  += am * a0.x;
            pp[1]  += ap * a0.y;  pm[1]  += am * a0.y;
            pp[2]  += ap * a0.z;  pm[2]  += am * a0.z;
            pp[3]  += ap * a0.w;  pm[3]  += am * a0.w;
            pp[4]  += ap * a1.x;  pm[4]  += am * a1.x;
            pp[5]  += ap * a1.y;  pm[5]  += am * a1.y;
            pp[6]  += ap * a1.z;  pm[6]  += am * a1.z;
            pp[7]  += ap * a1.w;  pm[7]  += am * a1.w;
            pp[8]  += ap * a2.x;  pm[8]  += am * a2.x;
            pp[9]  += ap * a2.y;  pm[9]  += am * a2.y;
            pp[10] += ap * a2.z;  pm[10] += am * a2.z;
            pp[11] += ap * a2.w;  pm[11] += am * a2.w;
            pp[12] += ap * a3.x;  pm[12] += am * a3.x;
            pp[13] += ap * a3.y;  pm[13] += am * a3.y;
            pp[14] += ap * a3.z;  pm[14] += am * a3.z;
            pp[15] += ap * a3.w;  pm[15] += am * a3.w;
        }
        __syncthreads();   // done reading tile t; its buffer may be overwritten
    }

    // ── Epilogue: pre-dot lane's 16 columns with mu_w / sigma_w ──
    const float4* __restrict__ mw4 = reinterpret_cast<const float4*>(mu_w);
    const float4* __restrict__ sw4 = reinterpret_cast<const float4*>(sigma_w);
    float t0 = 0.f, t1 = 0.f, t2 = 0.f, t3 = 0.f;
#pragma unroll
    for (int k = 0; k < 4; k++) {
        float4 mw = mw4[s + 8 * k];
        float4 sw = sw4[s + 8 * k];
        t0 += pp[4*k]*mw.x + pp[4*k+1]*mw.y + pp[4*k+2]*mw.z + pp[4*k+3]*mw.w;
        t1 += pm[4*k]*mw.x + pm[4*k+1]*mw.y + pm[4*k+2]*mw.z + pm[4*k+3]*mw.w;
        t2 += pp[4*k]*sw.x + pp[4*k+1]*sw.y + pp[4*k+2]*sw.z + pp[4*k+3]*sw.w;
        t3 += pm[4*k]*sw.x + pm[4*k+1]*sw.y + pm[4*k+2]*sw.z + pm[4*k+3]*sw.w;
    }
#pragma unroll
    for (int off = 16; off > 0; off >>= 1) {
        t0 += __shfl_xor_sync(0xffffffffu, t0, off);
        t1 += __shfl_xor_sync(0xffffffffu, t1, off);
        t2 += __shfl_xor_sync(0xffffffffu, t2, off);
        t3 += __shfl_xor_sync(0xffffffffu, t3, off);
        sp += __shfl_xor_sync(0xffffffffu, sp, off);
        sm += __shfl_xor_sync(0xffffffffu, sm, off);
    }
    if (lane == 0) {
        wsum[warp][0] = t0;
        wsum[warp][1] = t1;
        wsum[warp][2] = t2;
        wsum[warp][3] = t3;
        wsum[warp][4] = sp * 0.125f;   // each row's a counted by 8 lanes of its oct
        wsum[warp][5] = sm * 0.125f;
    }
    __syncthreads();
    if (tid < 6) {
        float ssum = 0.f;
#pragma unroll
        for (int w = 0; w < WPB; w++) ssum += wsum[w][tid];
        g_part[tid][b] = ssum;
    }
    __threadfence();
    __syncthreads();
    if (tid == 0)
        is_last = (atomicAdd(&g_count, 1) == NBLK - 1) ? 1 : 0;
    __syncthreads();
    if (!is_last) return;

    // ── Last block: final 6-scalar reduce + the 8 outputs ──
    __shared__ float tot[6];
    if (warp < 6) {
        float ssum = 0.f;
#pragma unroll
        for (int i = 0; i < (NBLK + 31) / 32; i++) {
            int j = lane + i * 32;
            if (j < NBLK) ssum += __ldcg(&g_part[warp][j]);
        }
#pragma unroll
        for (int off = 16; off > 0; off >>= 1)
            ssum += __shfl_xor_sync(0xffffffffu, ssum, off);
        if (lane == 0) tot[warp] = ssum;
    }
    __syncthreads();
    if (tid < 4) {
        const float Sp = fmaxf(tot[4], 1e-6f);
        const float Sm = fmaxf(tot[5], 1e-6f);
        float wk = w_key[tid];
        float wv = w_value[tid];
        bool pos = (wk > 0.f);
        float dmu = pos ? (tot[0] / Sp) : (tot[1] / Sm);
        float dsg = pos ? (tot[2] / Sp) : (tot[3] / Sm);
        float mu_z = wv * dmu + mu_b[0];
        float x = wv * dsg + sigma_b[0];
        float sig_z = fmaxf(x, 0.f) + log1pf(expf(-fabsf(x)));
        out[tid] = mu_z;
        out[4 + tid] = sig_z;
    }
    if (tid == 0) g_count = 0;   // reset for next graph replay
}

extern "C" void kernel_launch(void* const* d_in, const int* in_sizes, int n_in,
                              void* d_out, int out_size) {
    const float* e       = (const float*)d_in[0];
    const float* w_key   = (const float*)d_in[1];
    const float* w_value = (const float*)d_in[2];
    const float* q       = (const float*)d_in[3];
    const float* mu_w    = (const float*)d_in[4];
    const float* mu_b    = (const float*)d_in[5];
    const float* sigma_w = (const float*)d_in[6];
    const float* sigma_b = (const float*)d_in[7];
    float* out = (float*)d_out;

    fp_r10<<<NBLK, NTHREADS>>>(e, q, mu_w, sigma_w, w_key, w_value, mu_b, sigma_b, out);
}

// round 11
// speedup vs baseline: 1.1889x; 1.1889x over previous
#include <cuda_runtime.h>
#include <math.h>

#define NS 100000
#define NPAIR (NS / 2)
#define H 128
#define NBLK 592            // 4 blocks/SM * 148 SMs
#define NTHREADS 256
#define WPB (NTHREADS / 32)
#define TOTW (NBLK * WPB)   // 4736 warps

// Per-block partials: 0:t_mu+ 1:t_mu- 2:t_sig+ 3:t_sig- 4:S+ 5:S-
__device__ float g_part[6][NBLK];
__device__ int g_count = 0;

__device__ __forceinline__ float dot8(float4 a, float4 b, float4 x, float4 y) {
    return a.x * x.x + a.y * x.y + a.z * x.z + a.w * x.w +
           b.x * y.x + b.y * y.y + b.z * y.z + b.w * y.w;
}

__global__ __launch_bounds__(NTHREADS, 4) void fp_r11(
    const float* __restrict__ e, const float* __restrict__ q,
    const float* __restrict__ mu_w, const float* __restrict__ sigma_w,
    const float* __restrict__ w_key, const float* __restrict__ w_value,
    const float* __restrict__ mu_b, const float* __restrict__ sigma_b,
    float* __restrict__ out) {
    const int lane = threadIdx.x & 31;
    const int warp = threadIdx.x >> 5;
    const int sub  = lane & 15;   // lane within 16-lane row group
    const int half = lane >> 4;   // which row of the pair
    const int gw = blockIdx.x * WPB + warp;

    const float4* __restrict__ e4 = reinterpret_cast<const float4*>(e);
    const float4* __restrict__ q4 = reinterpret_cast<const float4*>(q);

    // per-lane fragments: q (pre-scaled by 1/||q||), mu_w, sigma_w
    float4 q0 = q4[sub * 2 + 0];
    float4 q1 = q4[sub * 2 + 1];
    float qn = dot8(q0, q1, q0, q1);
#pragma unroll
    for (int o = 8; o > 0; o >>= 1) qn += __shfl_xor_sync(0xffffffffu, qn, o);
    const float rq = rsqrtf(qn);
    q0.x *= rq; q0.y *= rq; q0.z *= rq; q0.w *= rq;
    q1.x *= rq; q1.y *= rq; q1.z *= rq; q1.w *= rq;
    float4 mw0 = reinterpret_cast<const float4*>(mu_w)[sub * 2];
    float4 mw1 = reinterpret_cast<const float4*>(mu_w)[sub * 2 + 1];
    float4 sw0 = reinterpret_cast<const float4*>(sigma_w)[sub * 2];
    float4 sw1 = reinterpret_cast<const float4*>(sigma_w)[sub * 2 + 1];

    // scalar accumulators only — rows die right after their 4 dots
    float t0 = 0.f, t1 = 0.f, t2 = 0.f, t3 = 0.f;
    float sp = 0.f, sm = 0.f;

    int p = gw;
    for (; p + TOTW < NPAIR; p += 2 * TOTW) {
        const int ia = (2 * p + half) * 32 + sub * 2;
        const int ib = (2 * (p + TOTW) + half) * 32 + sub * 2;
        float4 a0 = e4[ia], a1 = e4[ia + 1];
        float4 b0 = e4[ib], b1 = e4[ib + 1];

        // 4 dots per row; a/b registers are DEAD after this block,
        // so next iteration's loads can be hoisted into the tree's shadow.
        float da = dot8(a0, a1, q0, q1);
        float na = dot8(a0, a1, a0, a1);
        float ma = dot8(a0, a1, mw0, mw1);
        float sa = dot8(a0, a1, sw0, sw1);
        float db = dot8(b0, b1, q0, q1);
        float nb = dot8(b0, b1, b0, b1);
        float mb = dot8(b0, b1, mw0, mw1);
        float sb = dot8(b0, b1, sw0, sw1);

        // only d,n need the cross-lane tree (m,s stay per-lane partials)
#pragma unroll
        for (int o = 8; o > 0; o >>= 1) {
            da += __shfl_xor_sync(0xffffffffu, da, o);
            na += __shfl_xor_sync(0xffffffffu, na, o);
            db += __shfl_xor_sync(0xffffffffu, db, o);
            nb += __shfl_xor_sync(0xffffffffu, nb, o);
        }
        float ra = rsqrtf(na);
        float rb = rsqrtf(nb);
        float apa = fmaxf(da, 0.f) * ra, ama = fmaxf(-da, 0.f) * ra;
        float apb = fmaxf(db, 0.f) * rb, amb = fmaxf(-db, 0.f) * rb;
        sp += apa + apb;
        sm += ama + amb;
        t0 += apa * ma + apb * mb;
        t1 += ama * ma + amb * mb;
        t2 += apa * sa + apb * sb;
        t3 += ama * sa + amb * sb;
    }
    if (p < NPAIR) {
        const int ia = (2 * p + half) * 32 + sub * 2;
        float4 a0 = e4[ia], a1 = e4[ia + 1];
        float da = dot8(a0, a1, q0, q1);
        float na = dot8(a0, a1, a0, a1);
        float ma = dot8(a0, a1, mw0, mw1);
        float sa = dot8(a0, a1, sw0, sw1);
#pragma unroll
        for (int o = 8; o > 0; o >>= 1) {
            da += __shfl_xor_sync(0xffffffffu, da, o);
            na += __shfl_xor_sync(0xffffffffu, na, o);
        }
        float ra = rsqrtf(na);
        float apa = fmaxf(da, 0.f) * ra, ama = fmaxf(-da, 0.f) * ra;
        sp += apa;  sm += ama;
        t0 += apa * ma;  t1 += ama * ma;
        t2 += apa * sa;  t3 += ama * sa;
    }

    // ── Warp epilogue: one 5-stage reduce over all 32 lanes ──
#pragma unroll
    for (int o = 16; o > 0; o >>= 1) {
        t0 += __shfl_xor_sync(0xffffffffu, t0, o);
        t1 += __shfl_xor_sync(0xffffffffu, t1, o);
        t2 += __shfl_xor_sync(0xffffffffu, t2, o);
        t3 += __shfl_xor_sync(0xffffffffu, t3, o);
        sp += __shfl_xor_sync(0xffffffffu, sp, o);
        sm += __shfl_xor_sync(0xffffffffu, sm, o);
    }

    __shared__ float wsum[WPB][6];
    __shared__ int is_last;
    if (lane == 0) {
        wsum[warp][0] = t0;
        wsum[warp][1] = t1;
        wsum[warp][2] = t2;
        wsum[warp][3] = t3;
        wsum[warp][4] = sp * 0.0625f;   // each row's a counted by its 16-lane group
        wsum[warp][5] = sm * 0.0625f;
    }
    __syncthreads();
    if (threadIdx.x < 6) {
        float s = 0.f;
#pragma unroll
        for (int w = 0; w < WPB; w++) s += wsum[w][threadIdx.x];
        g_part[threadIdx.x][blockIdx.x] = s;
    }
    __threadfence();
    __syncthreads();
    if (threadIdx.x == 0)
        is_last = (atomicAdd(&g_count, 1) == NBLK - 1) ? 1 : 0;
    __syncthreads();
    if (!is_last) return;

    // ── Last block: final 6-scalar reduce + the 8 outputs ──
    __shared__ float tot[6];
    if (warp < 6) {
        float s = 0.f;
#pragma unroll
        for (int i = 0; i < (NBLK + 31) / 32; i++) {
            int j = lane + i * 32;
            if (j < NBLK) s += __ldcg(&g_part[warp][j]);
        }
#pragma unroll
        for (int o = 16; o > 0; o >>= 1) s += __shfl_xor_sync(0xffffffffu, s, o);
        if (lane == 0) tot[warp] = s;
    }
    __syncthreads();
    if (threadIdx.x < 4) {
        const int t = threadIdx.x;
        const float Sp = fmaxf(tot[4], 1e-6f);
        const float Sm = fmaxf(tot[5], 1e-6f);
        float wk = w_key[t];
        float wv = w_value[t];
        bool pos = (wk > 0.f);
        float dmu = pos ? (tot[0] / Sp) : (tot[1] / Sm);
        float dsg = pos ? (tot[2] / Sp) : (tot[3] / Sm);
        float mu_z = wv * dmu + mu_b[0];
        float x = wv * dsg + sigma_b[0];
        float sig_z = fmaxf(x, 0.f) + log1pf(expf(-fabsf(x)));
        out[t] = mu_z;
        out[4 + t] = sig_z;
    }
    if (threadIdx.x == 0) g_count = 0;  // reset for next graph replay
}

extern "C" void kernel_launch(void* const* d_in, const int* in_sizes, int n_in,
                              void* d_out, int out_size) {
    const float* e       = (const float*)d_in[0];
    const float* w_key   = (const float*)d_in[1];
    const float* w_value = (const float*)d_in[2];
    const float* q       = (const float*)d_in[3];
    const float* mu_w    = (const float*)d_in[4];
    const float* mu_b    = (const float*)d_in[5];
    const float* sigma_w = (const float*)d_in[6];
    const float* sigma_b = (const float*)d_in[7];
    float* out = (float*)d_out;

    fp_r11<<<NBLK, NTHREADS>>>(e, q, mu_w, sigma_w, w_key, w_value, mu_b, sigma_b, out);
}

// round 12
// speedup vs baseline: 1.3145x; 1.1057x over previous
#include <cuda_runtime.h>
#include <math.h>

#define NS 100000
#define NQUAD (NS / 4)      // 25000 quads of 4 consecutive rows
#define H 128
#define NBLK 740            // 5 blocks/SM * 148 SMs (128-thread blocks)
#define NTHREADS 128
#define WPB 4
#define TOTW (NBLK * WPB)   // 2960 warps

typedef unsigned long long ull;

// Per-block partials: 0:t_mu+ 1:t_mu- 2:t_sig+ 3:t_sig- 4:S+ 5:S-
__device__ float g_part[6][NBLK];
__device__ int g_count = 0;

// Blackwell packed f32x2 FMA (PTX-only; one SASS FFMA2 does 2 lanes of fp32 fma)
__device__ __forceinline__ ull ff2(ull a, ull b, ull c) {
    ull r;
    asm("fma.rn.f32x2 %0, %1, %2, %3;" : "=l"(r) : "l"(a), "l"(b), "l"(c));
    return r;
}
__device__ __forceinline__ ull pack2(float lo, float hi) {
    ull r;
    asm("mov.b64 %0, {%1, %2};" : "=l"(r) : "f"(lo), "f"(hi));
    return r;
}
__device__ __forceinline__ float sum2(ull a) {
    float lo, hi;
    asm("mov.b64 {%0, %1}, %2;" : "=f"(lo), "=f"(hi) : "l"(a));
    return lo + hi;
}
__device__ __forceinline__ float d4f(float4 a, float4 b) {
    return a.x * b.x + a.y * b.y + a.z * b.z + a.w * b.w;
}

__global__ __launch_bounds__(NTHREADS, 5) void fp_r12(
    const float* __restrict__ e, const float* __restrict__ q,
    const float* __restrict__ mu_w, const float* __restrict__ sigma_w,
    const float* __restrict__ w_key, const float* __restrict__ w_value,
    const float* __restrict__ mu_b, const float* __restrict__ sigma_b,
    float* __restrict__ out) {
    const int tid = threadIdx.x;
    const int lane = tid & 31;
    const int warp = tid >> 5;
    const int s = lane & 7;      // column slot within 8-lane row group
    const int g = lane >> 3;     // which of the 4 rows in the quad

    // ── one-time fragment setup: q̂, mu_w, sigma_w (16 floats each, packed) ──
    const float4* __restrict__ q4p = reinterpret_cast<const float4*>(q);
    float4 qa = q4p[s], qb = q4p[s + 8], qc = q4p[s + 16], qe = q4p[s + 24];
    float qn = d4f(qa, qa) + d4f(qb, qb) + d4f(qc, qc) + d4f(qe, qe);
    qn += __shfl_xor_sync(0xffffffffu, qn, 1);
    qn += __shfl_xor_sync(0xffffffffu, qn, 2);
    qn += __shfl_xor_sync(0xffffffffu, qn, 4);
    const float rq = rsqrtf(qn);
    ull qf[8];
    qf[0] = pack2(qa.x * rq, qa.y * rq);  qf[1] = pack2(qa.z * rq, qa.w * rq);
    qf[2] = pack2(qb.x * rq, qb.y * rq);  qf[3] = pack2(qb.z * rq, qb.w * rq);
    qf[4] = pack2(qc.x * rq, qc.y * rq);  qf[5] = pack2(qc.z * rq, qc.w * rq);
    qf[6] = pack2(qe.x * rq, qe.y * rq);  qf[7] = pack2(qe.z * rq, qe.w * rq);
    const float4* __restrict__ m4p = reinterpret_cast<const float4*>(mu_w);
    const float4* __restrict__ s4p = reinterpret_cast<const float4*>(sigma_w);
    ull mf[8], sf[8];
#pragma unroll
    for (int k = 0; k < 4; k++) {
        float4 m = m4p[s + 8 * k];
        float4 w = s4p[s + 8 * k];
        mf[2 * k]     = pack2(m.x, m.y);
        mf[2 * k + 1] = pack2(m.z, m.w);
        sf[2 * k]     = pack2(w.x, w.y);
        sf[2 * k + 1] = pack2(w.z, w.w);
    }

    // packed accumulators
    ull t0 = 0, t1 = 0, t2 = 0, t3 = 0;
    float spa = 0.f, sma = 0.f;

    // ── main loop: one quad (4 rows, 2048B) per warp-iteration ──
    const ulonglong2* __restrict__ e16 = reinterpret_cast<const ulonglong2*>(e);
    int qd = blockIdx.x * WPB + warp;
    const ulonglong2* rp = e16 + ((size_t)qd * 4 + g) * 32 + s;
    const size_t pstride = (size_t)TOTW * 4 * 32;
    for (; qd < NQUAD; qd += TOTW, rp += pstride) {
        ulonglong2 c0 = rp[0];
        ulonglong2 c1 = rp[8];
        ulonglong2 c2 = rp[16];
        ulonglong2 c3 = rp[24];
        ull v0 = c0.x, v1 = c0.y, v2 = c1.x, v3 = c1.y;
        ull v4 = c2.x, v5 = c2.y, v6 = c3.x, v7 = c3.y;

        ull d2 = 0, n2 = 0, m2 = 0, s2 = 0;
        d2 = ff2(v0, qf[0], d2); n2 = ff2(v0, v0, n2); m2 = ff2(v0, mf[0], m2); s2 = ff2(v0, sf[0], s2);
        d2 = ff2(v1, qf[1], d2); n2 = ff2(v1, v1, n2); m2 = ff2(v1, mf[1], m2); s2 = ff2(v1, sf[1], s2);
        d2 = ff2(v2, qf[2], d2); n2 = ff2(v2, v2, n2); m2 = ff2(v2, mf[2], m2); s2 = ff2(v2, sf[2], s2);
        d2 = ff2(v3, qf[3], d2); n2 = ff2(v3, v3, n2); m2 = ff2(v3, mf[3], m2); s2 = ff2(v3, sf[3], s2);
        d2 = ff2(v4, qf[4], d2); n2 = ff2(v4, v4, n2); m2 = ff2(v4, mf[4], m2); s2 = ff2(v4, sf[4], s2);
        d2 = ff2(v5, qf[5], d2); n2 = ff2(v5, v5, n2); m2 = ff2(v5, mf[5], m2); s2 = ff2(v5, sf[5], s2);
        d2 = ff2(v6, qf[6], d2); n2 = ff2(v6, v6, n2); m2 = ff2(v6, mf[6], m2); s2 = ff2(v6, sf[6], s2);
        d2 = ff2(v7, qf[7], d2); n2 = ff2(v7, v7, n2); m2 = ff2(v7, mf[7], m2); s2 = ff2(v7, sf[7], s2);

        float d = sum2(d2);
        float n = sum2(n2);
        // 3-stage butterfly over the 8-lane group (reduces all 4 rows at once)
        d += __shfl_xor_sync(0xffffffffu, d, 1);
        n += __shfl_xor_sync(0xffffffffu, n, 1);
        d += __shfl_xor_sync(0xffffffffu, d, 2);
        n += __shfl_xor_sync(0xffffffffu, n, 2);
        d += __shfl_xor_sync(0xffffffffu, d, 4);
        n += __shfl_xor_sync(0xffffffffu, n, 4);

        float r = rsqrtf(n);
        float ap = fmaxf(d, 0.f) * r;
        float am = fmaxf(-d, 0.f) * r;
        spa += ap;
        sma += am;
        ull ap2 = pack2(ap, ap);
        ull am2 = pack2(am, am);
        t0 = ff2(ap2, m2, t0);
        t1 = ff2(am2, m2, t1);
        t2 = ff2(ap2, s2, t2);
        t3 = ff2(am2, s2, t3);
    }

    // ── warp epilogue ──
    float u0 = sum2(t0), u1 = sum2(t1), u2 = sum2(t2), u3 = sum2(t3);
#pragma unroll
    for (int o = 16; o > 0; o >>= 1) {
        u0 += __shfl_xor_sync(0xffffffffu, u0, o);
        u1 += __shfl_xor_sync(0xffffffffu, u1, o);
        u2 += __shfl_xor_sync(0xffffffffu, u2, o);
        u3 += __shfl_xor_sync(0xffffffffu, u3, o);
        spa += __shfl_xor_sync(0xffffffffu, spa, o);
        sma += __shfl_xor_sync(0xffffffffu, sma, o);
    }

    __shared__ float wsum[WPB][6];
    __shared__ int is_last;
    if (lane == 0) {
        wsum[warp][0] = u0;
        wsum[warp][1] = u1;
        wsum[warp][2] = u2;
        wsum[warp][3] = u3;
        wsum[warp][4] = spa * 0.125f;   // each row's a counted by its 8 lanes
        wsum[warp][5] = sma * 0.125f;
    }
    __syncthreads();
    if (tid < 6) {
        float acc = 0.f;
#pragma unroll
        for (int w = 0; w < WPB; w++) acc += wsum[w][tid];
        g_part[tid][blockIdx.x] = acc;
    }
    __threadfence();
    __syncthreads();
    if (tid == 0)
        is_last = (atomicAdd(&g_count, 1) == NBLK - 1) ? 1 : 0;
    __syncthreads();
    if (!is_last) return;

    // ── last block: final 6-scalar reduce (4 warps cover 6 quantities) ──
    __shared__ float tot[6];
    for (int qq = warp; qq < 6; qq += WPB) {
        float acc = 0.f;
#pragma unroll
        for (int i = 0; i < (NBLK + 31) / 32; i++) {
            int j = lane + i * 32;
            if (j < NBLK) acc += __ldcg(&g_part[qq][j]);
        }
#pragma unroll
        for (int o = 16; o > 0; o >>= 1)
            acc += __shfl_xor_sync(0xffffffffu, acc, o);
        if (lane == 0) tot[qq] = acc;
    }
    __syncthreads();
    if (tid < 4) {
        const float Sp = fmaxf(tot[4], 1e-6f);
        const float Sm = fmaxf(tot[5], 1e-6f);
        float wk = w_key[tid];
        float wv = w_value[tid];
        bool pos = (wk > 0.f);
        float dmu = pos ? (tot[0] / Sp) : (tot[1] / Sm);
        float dsg = pos ? (tot[2] / Sp) : (tot[3] / Sm);
        float mu_z = wv * dmu + mu_b[0];
        float x = wv * dsg + sigma_b[0];
        float sig_z = fmaxf(x, 0.f) + log1pf(expf(-fabsf(x)));
        out[tid] = mu_z;
        out[4 + tid] = sig_z;
    }
    if (tid == 0) g_count = 0;  // reset for next graph replay
}

extern "C" void kernel_launch(void* const* d_in, const int* in_sizes, int n_in,
                              void* d_out, int out_size) {
    const float* e       = (const float*)d_in[0];
    const float* w_key   = (const float*)d_in[1];
    const float* w_value = (const float*)d_in[2];
    const float* q       = (const float*)d_in[3];
    const float* mu_w    = (const float*)d_in[4];
    const float* mu_b    = (const float*)d_in[5];
    const float* sigma_w = (const float*)d_in[6];
    const float* sigma_b = (const float*)d_in[7];
    float* out = (float*)d_out;

    fp_r12<<<NBLK, NTHREADS>>>(e, q, mu_w, sigma_w, w_key, w_value, mu_b, sigma_b, out);
}